// round 1
// baseline (speedup 1.0000x reference)
#include <cuda_runtime.h>
#include <math.h>

#define NB 8
#define NT 2048
#define NC 2048
#define NHS 128
#define NM (NB*NT)

// scratch for projected/roped q, k and plain v  (fp32, [NM][NHS])
__device__ float g_q[(size_t)NM*NHS];
__device__ float g_k[(size_t)NM*NHS];
__device__ float g_v[(size_t)NM*NHS];

// ---------------------------------------------------------------------------
// Kernel A: fused projection + RoPE.
// grid (NM/64, 3): y=0 -> k (Wk, rope), y=1 -> q (Wq, rope), y=2 -> v (Wv).
// block 256 threads: tx = tid&15 (8 cols each), ty = tid>>4 (4 rows each).
// ---------------------------------------------------------------------------
__global__ __launch_bounds__(256) void proj_rope_kernel(
    const float* __restrict__ x, const float* __restrict__ Wk,
    const float* __restrict__ Wq, const float* __restrict__ Wv)
{
    constexpr int BM = 64, BK = 32;
    __shared__ float sxT[BK][68];     // transposed x tile: [k][row], pad for LDS.128
    __shared__ float sw[BK][NHS];     // W tile: [k][col]

    const int tid = threadIdx.x;
    const int tx = tid & 15, ty = tid >> 4;
    const int mbase = blockIdx.x * BM;
    const int which = blockIdx.y;
    const float* W = (which == 0) ? Wk : (which == 1) ? Wq : Wv;
    float* outp    = (which == 0) ? g_k : (which == 1) ? g_q : g_v;

    float acc[4][8];
    #pragma unroll
    for (int i = 0; i < 4; i++)
        #pragma unroll
        for (int j = 0; j < 8; j++) acc[i][j] = 0.f;

    for (int kt = 0; kt < NC; kt += BK) {
        // x tile: 64 rows x 32 k -> transposed smem
        #pragma unroll
        for (int u = 0; u < 2; u++) {
            int f4 = u * 256 + tid;
            int row = f4 >> 3, cf = f4 & 7;
            float4 v = *reinterpret_cast<const float4*>(
                &x[(size_t)(mbase + row) * NC + kt + cf * 4]);
            sxT[cf*4+0][row] = v.x; sxT[cf*4+1][row] = v.y;
            sxT[cf*4+2][row] = v.z; sxT[cf*4+3][row] = v.w;
        }
        // W tile: 32 k x 128 cols
        #pragma unroll
        for (int u = 0; u < 4; u++) {
            int f4 = u * 256 + tid;
            int row = f4 >> 5, cf = f4 & 31;
            *reinterpret_cast<float4*>(&sw[row][cf * 4]) =
                *reinterpret_cast<const float4*>(&W[(size_t)(kt + row) * NHS + cf * 4]);
        }
        __syncthreads();
        #pragma unroll
        for (int kk = 0; kk < BK; kk++) {
            float4 a4 = *reinterpret_cast<const float4*>(&sxT[kk][ty * 4]);
            float4 b0 = *reinterpret_cast<const float4*>(&sw[kk][tx * 8]);
            float4 b1 = *reinterpret_cast<const float4*>(&sw[kk][tx * 8 + 4]);
            float a[4] = {a4.x, a4.y, a4.z, a4.w};
            float b[8] = {b0.x, b0.y, b0.z, b0.w, b1.x, b1.y, b1.z, b1.w};
            #pragma unroll
            for (int i = 0; i < 4; i++)
                #pragma unroll
                for (int j = 0; j < 8; j++)
                    acc[i][j] = fmaf(a[i], b[j], acc[i][j]);
        }
        __syncthreads();
    }

    // epilogue: rope for q/k, plain store for v
    const float L2T = 13.287712379549449f / 64.f;   // log2(10000)/64
    #pragma unroll
    for (int i = 0; i < 4; i++) {
        int row = mbase + ty * 4 + i;
        float* orow = &outp[(size_t)row * NHS + tx * 8];
        if (which == 2) {
            #pragma unroll
            for (int j = 0; j < 8; j++) orow[j] = acc[i][j];
        } else {
            float tpos = (float)(row & (NT - 1));   // t = row % T
            #pragma unroll
            for (int j = 0; j < 8; j += 2) {
                int p = (tx * 8 + j) >> 1;          // pair index
                float freq = exp2f(-(float)p * L2T);
                float sn, cs;
                sincosf(tpos * freq, &sn, &cs);
                orow[j]   = acc[i][j] * cs - acc[i][j + 1] * sn;
                orow[j+1] = acc[i][j] * sn + acc[i][j + 1] * cs;
            }
        }
    }
}

// ---------------------------------------------------------------------------
// Kernel B: causal flash attention over g_q/g_k/g_v.
// grid (NT/64, NB). block 256: tx = tid&15, ty = tid>>4.
// Per chunk: S(64x64) via TM4/TN4 regs, online softmax, O += P*V (TM4/TN8).
// ---------------------------------------------------------------------------
#define SMEM_ATTN_FLOATS (128*68 + 64*129 + 64*65 + 64*16 + 192)

__global__ __launch_bounds__(256) void attn_kernel(float* __restrict__ out)
{
    extern __shared__ float sm[];
    float* sQT  = sm;                    // [128][68] transposed, pre-scaled Q
    float* sKV  = sQT + 128 * 68;        // K as [64][129]  /  V as [64][128]
    float* sP   = sKV + 64 * 129;        // [64][65]
    float* red  = sP  + 64 * 65;         // [64][16]
    float* srm  = red + 64 * 16;         // row max
    float* srl  = srm + 64;              // row sum l
    float* sfac = srl + 64;              // exp(m_old - m_new)

    const int tid = threadIdx.x;
    const int tx = tid & 15, ty = tid >> 4;
    const int qblock = blockIdx.x;
    const int bb = blockIdx.y;
    const int q0 = qblock * 64;
    const size_t rowbase = (size_t)bb * NT;
    const float scale = 0.08838834764831845f;   // 128^-0.5

    if (tid < 64) { srm[tid] = -1e30f; srl[tid] = 0.f; }

    // load Q, pre-scale, transpose
    #pragma unroll
    for (int u = 0; u < 8; u++) {
        int f4 = u * 256 + tid;
        int row = f4 >> 5, cf = f4 & 31;
        float4 v = *reinterpret_cast<const float4*>(
            &g_q[(rowbase + q0 + row) * NHS + cf * 4]);
        sQT[(cf*4+0)*68 + row] = v.x * scale;
        sQT[(cf*4+1)*68 + row] = v.y * scale;
        sQT[(cf*4+2)*68 + row] = v.z * scale;
        sQT[(cf*4+3)*68 + row] = v.w * scale;
    }

    float O[4][8];
    #pragma unroll
    for (int i = 0; i < 4; i++)
        #pragma unroll
        for (int j = 0; j < 8; j++) O[i][j] = 0.f;

    for (int c = 0; c <= qblock; c++) {
        __syncthreads();                                   // (1)
        // load K chunk -> sKV [key][129], scalar, conflict-free
        const float* kg = &g_k[(rowbase + (size_t)c * 64) * NHS];
        #pragma unroll
        for (int u = 0; u < 32; u++) {
            int flat = u * 256 + tid;
            int key = flat >> 7, col = flat & 127;
            sKV[key * 129 + col] = kg[(size_t)key * NHS + col];
        }
        __syncthreads();                                   // (2)

        // S = (Q*scale) . K^T  -> s[rows 4ty..][keys 4tx..]
        float s[4][4];
        #pragma unroll
        for (int i = 0; i < 4; i++)
            #pragma unroll
            for (int j = 0; j < 4; j++) s[i][j] = 0.f;
        #pragma unroll 4
        for (int k = 0; k < NHS; k++) {
            float4 a4 = *reinterpret_cast<const float4*>(&sQT[k * 68 + ty * 4]);
            float a[4] = {a4.x, a4.y, a4.z, a4.w};
            float b[4];
            #pragma unroll
            for (int j = 0; j < 4; j++) b[j] = sKV[(4 * tx + j) * 129 + k];
            #pragma unroll
            for (int i = 0; i < 4; i++)
                #pragma unroll
                for (int j = 0; j < 4; j++)
                    s[i][j] = fmaf(a[i], b[j], s[i][j]);
        }
        // causal mask on diagonal chunk
        if (c == qblock) {
            #pragma unroll
            for (int i = 0; i < 4; i++)
                #pragma unroll
                for (int j = 0; j < 4; j++)
                    if (4 * tx + j > 4 * ty + i) s[i][j] = -1e30f;
        }
        // per-thread row max -> red
        #pragma unroll
        for (int i = 0; i < 4; i++) {
            float rm = fmaxf(fmaxf(s[i][0], s[i][1]), fmaxf(s[i][2], s[i][3]));
            red[(4 * ty + i) * 16 + tx] = rm;
        }
        __syncthreads();                                   // (3)
        if (tid < 64) {
            float m = red[tid * 16];
            #pragma unroll
            for (int r = 1; r < 16; r++) m = fmaxf(m, red[tid * 16 + r]);
            float m_old = srm[tid];
            float m_new = fmaxf(m_old, m);
            sfac[tid] = __expf(m_old - m_new);
            srm[tid]  = m_new;
        }
        __syncthreads();                                   // (4)

        // P = exp(s - m); row partial sums
        #pragma unroll
        for (int i = 0; i < 4; i++) {
            int r = 4 * ty + i;
            float mr = srm[r];
            float sum = 0.f;
            #pragma unroll
            for (int j = 0; j < 4; j++) {
                float p = __expf(s[i][j] - mr);
                sP[r * 65 + 4 * tx + j] = p;
                sum += p;
            }
            red[r * 16 + tx] = sum;
        }
        // load V chunk -> sKV [key][128] (K reads finished two syncs ago)
        const float4* vg = reinterpret_cast<const float4*>(
            &g_v[(rowbase + (size_t)c * 64) * NHS]);
        #pragma unroll
        for (int u = 0; u < 8; u++) {
            int f4 = u * 256 + tid;
            reinterpret_cast<float4*>(sKV)[f4] = vg[f4];
        }
        __syncthreads();                                   // (5)
        if (tid < 64) {
            float sum = red[tid * 16];
            #pragma unroll
            for (int r = 1; r < 16; r++) sum += red[tid * 16 + r];
            srl[tid] = srl[tid] * sfac[tid] + sum;
        }
        // rescale O, then O += P.V
        #pragma unroll
        for (int i = 0; i < 4; i++) {
            float f = sfac[4 * ty + i];
            #pragma unroll
            for (int j = 0; j < 8; j++) O[i][j] *= f;
        }
        #pragma unroll 4
        for (int key = 0; key < 64; key++) {
            float a[4];
            #pragma unroll
            for (int i = 0; i < 4; i++) a[i] = sP[(4 * ty + i) * 65 + key];
            float4 b0 = *reinterpret_cast<const float4*>(&sKV[key * 128 + tx * 8]);
            float4 b1 = *reinterpret_cast<const float4*>(&sKV[key * 128 + tx * 8 + 4]);
            float b[8] = {b0.x, b0.y, b0.z, b0.w, b1.x, b1.y, b1.z, b1.w};
            #pragma unroll
            for (int i = 0; i < 4; i++)
                #pragma unroll
                for (int j = 0; j < 8; j++)
                    O[i][j] = fmaf(a[i], b[j], O[i][j]);
        }
    }
    __syncthreads();
    #pragma unroll
    for (int i = 0; i < 4; i++) {
        int r = 4 * ty + i;
        float inv = 1.f / srl[r];
        float* orow = &out[(rowbase + q0 + r) * NHS + tx * 8];
        #pragma unroll
        for (int j = 0; j < 8; j++) orow[j] = O[i][j] * inv;
    }
}

// ---------------------------------------------------------------------------
extern "C" void kernel_launch(void* const* d_in, const int* in_sizes, int n_in,
                              void* d_out, int out_size)
{
    const float* x  = (const float*)d_in[0];
    const float* Wk = (const float*)d_in[1];
    const float* Wq = (const float*)d_in[2];
    const float* Wv = (const float*)d_in[3];
    float* out = (float*)d_out;

    (void)in_sizes; (void)n_in; (void)out_size;

    const size_t attn_smem = SMEM_ATTN_FLOATS * sizeof(float);
    cudaFuncSetAttribute(attn_kernel,
                         cudaFuncAttributeMaxDynamicSharedMemorySize,
                         (int)attn_smem);

    proj_rope_kernel<<<dim3(NM / 64, 3), 256>>>(x, Wk, Wq, Wv);
    attn_kernel<<<dim3(NT / 64, NB), 256, attn_smem>>>(out);
}

// round 2
// speedup vs baseline: 1.8666x; 1.8666x over previous
#include <cuda_runtime.h>
#include <math.h>
#include <stdint.h>

#define NB 8
#define NT 2048
#define NC 2048
#define NHS 128
#define NM (NB*NT)

// scratch for projected/roped q, k and plain v  (fp32, [NM][NHS])
__device__ float g_q[(size_t)NM*NHS];
__device__ float g_k[(size_t)NM*NHS];
__device__ float g_v[(size_t)NM*NHS];

__device__ __forceinline__ uint32_t f2tf(float f) {
    uint32_t r;
    asm("cvt.rna.tf32.f32 %0, %1;" : "=r"(r) : "f"(f));
    return r;
}

__device__ __forceinline__ void mma_tf32(float c[4], const uint32_t a[4],
                                         const uint32_t b[2]) {
    asm volatile(
        "mma.sync.aligned.m16n8k8.row.col.f32.tf32.tf32.f32 "
        "{%0,%1,%2,%3}, {%4,%5,%6,%7}, {%8,%9}, {%0,%1,%2,%3};"
        : "+f"(c[0]), "+f"(c[1]), "+f"(c[2]), "+f"(c[3])
        : "r"(a[0]), "r"(a[1]), "r"(a[2]), "r"(a[3]),
          "r"(b[0]), "r"(b[1]));
}

// ---------------------------------------------------------------------------
// Kernel A: fused projection + RoPE with tf32 mma.sync.
// grid (NM/128, 3): y=0 -> k (rope), y=1 -> q (rope), y=2 -> v.
// block 256 = 8 warps, warp grid 2(m) x 4(n), warp tile 64x32.
// ---------------------------------------------------------------------------
__global__ __launch_bounds__(256) void proj_rope_mma(
    const float* __restrict__ x, const float* __restrict__ Wk,
    const float* __restrict__ Wq, const float* __restrict__ Wv)
{
    constexpr int BK = 16;
    __shared__ uint32_t sA[128][20];    // tf32 bits, [m][k], stride 20 -> 0-conflict frags
    __shared__ uint32_t sB[16][136];    // tf32 bits, [k][n], stride 136 -> 0-conflict frags

    const int tid  = threadIdx.x;
    const int warp = tid >> 5, lane = tid & 31;
    const int wm = warp >> 2, wn = warp & 3;      // 2 x 4 warp grid
    const int g = lane >> 2, t = lane & 3;
    const int mbase = blockIdx.x * 128;
    const int which = blockIdx.y;
    const float* W = (which == 0) ? Wk : (which == 1) ? Wq : Wv;
    float* outp    = (which == 0) ? g_k : (which == 1) ? g_q : g_v;

    float c[4][4][4];                    // [im][in][frag]
    #pragma unroll
    for (int im = 0; im < 4; im++)
        #pragma unroll
        for (int in = 0; in < 4; in++)
            #pragma unroll
            for (int f = 0; f < 4; f++) c[im][in][f] = 0.f;

    // prefetch registers
    float4 pa[2], pb[2];

    // A tile: 128 rows x 16 k  = 512 float4; thread u*256+tid: row=idx>>2, cf=idx&3
    #pragma unroll
    for (int u = 0; u < 2; u++) {
        int idx = u * 256 + tid;
        int row = idx >> 2, cf = idx & 3;
        pa[u] = *reinterpret_cast<const float4*>(&x[(size_t)(mbase + row) * NC + cf * 4]);
    }
    // B tile: 16 k x 128 n = 512 float4; krow=idx>>5, cf=idx&31
    #pragma unroll
    for (int u = 0; u < 2; u++) {
        int idx = u * 256 + tid;
        int krow = idx >> 5, cf = idx & 31;
        pb[u] = *reinterpret_cast<const float4*>(&W[(size_t)krow * NHS + cf * 4]);
    }

    for (int it = 0; it < NC / BK; it++) {
        // stage prefetched tile -> smem (with tf32 rounding)
        #pragma unroll
        for (int u = 0; u < 2; u++) {
            int idx = u * 256 + tid;
            int row = idx >> 2, cf = idx & 3;
            sA[row][cf*4+0] = f2tf(pa[u].x); sA[row][cf*4+1] = f2tf(pa[u].y);
            sA[row][cf*4+2] = f2tf(pa[u].z); sA[row][cf*4+3] = f2tf(pa[u].w);
        }
        #pragma unroll
        for (int u = 0; u < 2; u++) {
            int idx = u * 256 + tid;
            int krow = idx >> 5, cf = idx & 31;
            sB[krow][cf*4+0] = f2tf(pb[u].x); sB[krow][cf*4+1] = f2tf(pb[u].y);
            sB[krow][cf*4+2] = f2tf(pb[u].z); sB[krow][cf*4+3] = f2tf(pb[u].w);
        }
        __syncthreads();

        // prefetch next tile
        if (it + 1 < NC / BK) {
            int kt = (it + 1) * BK;
            #pragma unroll
            for (int u = 0; u < 2; u++) {
                int idx = u * 256 + tid;
                int row = idx >> 2, cf = idx & 3;
                pa[u] = *reinterpret_cast<const float4*>(
                    &x[(size_t)(mbase + row) * NC + kt + cf * 4]);
            }
            #pragma unroll
            for (int u = 0; u < 2; u++) {
                int idx = u * 256 + tid;
                int krow = idx >> 5, cf = idx & 31;
                pb[u] = *reinterpret_cast<const float4*>(
                    &W[(size_t)(kt + krow) * NHS + cf * 4]);
            }
        }

        // compute: 2 k-steps of 8
        #pragma unroll
        for (int ks = 0; ks < 2; ks++) {
            int kb = ks * 8;
            uint32_t afr[4][4];
            #pragma unroll
            for (int im = 0; im < 4; im++) {
                int r0 = wm * 64 + im * 16 + g;
                afr[im][0] = sA[r0    ][kb + t    ];
                afr[im][1] = sA[r0 + 8][kb + t    ];
                afr[im][2] = sA[r0    ][kb + t + 4];
                afr[im][3] = sA[r0 + 8][kb + t + 4];
            }
            uint32_t bfr[4][2];
            #pragma unroll
            for (int in = 0; in < 4; in++) {
                int n0 = wn * 32 + in * 8 + g;
                bfr[in][0] = sB[kb + t    ][n0];
                bfr[in][1] = sB[kb + t + 4][n0];
            }
            #pragma unroll
            for (int im = 0; im < 4; im++)
                #pragma unroll
                for (int in = 0; in < 4; in++)
                    mma_tf32(c[im][in], afr[im], bfr[in]);
        }
        __syncthreads();
    }

    // epilogue: RoPE for q/k, plain store for v.
    // c0,c1 sit at cols (2t, 2t+1) -> exactly one rotation pair.
    const float L2T = 13.287712379549449f / 64.f;   // log2(10000)/64
    #pragma unroll
    for (int im = 0; im < 4; im++) {
        int r1 = mbase + wm * 64 + im * 16 + g;
        int r2 = r1 + 8;
        #pragma unroll
        for (int in = 0; in < 4; in++) {
            int n = wn * 32 + in * 8 + 2 * t;
            float2 lo = make_float2(c[im][in][0], c[im][in][1]);
            float2 hi = make_float2(c[im][in][2], c[im][in][3]);
            if (which == 2) {
                *reinterpret_cast<float2*>(&outp[(size_t)r1 * NHS + n]) = lo;
                *reinterpret_cast<float2*>(&outp[(size_t)r2 * NHS + n]) = hi;
            } else {
                int p = n >> 1;
                float freq = exp2f(-(float)p * L2T);
                float sn, cs;
                sincosf((float)(r1 & (NT - 1)) * freq, &sn, &cs);
                float2 o1 = make_float2(lo.x * cs - lo.y * sn,
                                        lo.x * sn + lo.y * cs);
                sincosf((float)(r2 & (NT - 1)) * freq, &sn, &cs);
                float2 o2 = make_float2(hi.x * cs - hi.y * sn,
                                        hi.x * sn + hi.y * cs);
                *reinterpret_cast<float2*>(&outp[(size_t)r1 * NHS + n]) = o1;
                *reinterpret_cast<float2*>(&outp[(size_t)r2 * NHS + n]) = o2;
            }
        }
    }
}

// ---------------------------------------------------------------------------
// Kernel B: causal flash attention over g_q/g_k/g_v.  (unchanged this round)
// ---------------------------------------------------------------------------
#define SMEM_ATTN_FLOATS (128*68 + 64*129 + 64*65 + 64*16 + 192)

__global__ __launch_bounds__(256) void attn_kernel(float* __restrict__ out)
{
    extern __shared__ float sm[];
    float* sQT  = sm;                    // [128][68] transposed, pre-scaled Q
    float* sKV  = sQT + 128 * 68;        // K as [64][129]  /  V as [64][128]
    float* sP   = sKV + 64 * 129;        // [64][65]
    float* red  = sP  + 64 * 65;         // [64][16]
    float* srm  = red + 64 * 16;         // row max
    float* srl  = srm + 64;              // row sum l
    float* sfac = srl + 64;              // exp(m_old - m_new)

    const int tid = threadIdx.x;
    const int tx = tid & 15, ty = tid >> 4;
    const int qblock = blockIdx.x;
    const int bb = blockIdx.y;
    const int q0 = qblock * 64;
    const size_t rowbase = (size_t)bb * NT;
    const float scale = 0.08838834764831845f;   // 128^-0.5

    if (tid < 64) { srm[tid] = -1e30f; srl[tid] = 0.f; }

    #pragma unroll
    for (int u = 0; u < 8; u++) {
        int f4 = u * 256 + tid;
        int row = f4 >> 5, cf = f4 & 31;
        float4 v = *reinterpret_cast<const float4*>(
            &g_q[(rowbase + q0 + row) * NHS + cf * 4]);
        sQT[(cf*4+0)*68 + row] = v.x * scale;
        sQT[(cf*4+1)*68 + row] = v.y * scale;
        sQT[(cf*4+2)*68 + row] = v.z * scale;
        sQT[(cf*4+3)*68 + row] = v.w * scale;
    }

    float O[4][8];
    #pragma unroll
    for (int i = 0; i < 4; i++)
        #pragma unroll
        for (int j = 0; j < 8; j++) O[i][j] = 0.f;

    for (int c = 0; c <= qblock; c++) {
        __syncthreads();
        const float* kg = &g_k[(rowbase + (size_t)c * 64) * NHS];
        #pragma unroll
        for (int u = 0; u < 32; u++) {
            int flat = u * 256 + tid;
            int key = flat >> 7, col = flat & 127;
            sKV[key * 129 + col] = kg[(size_t)key * NHS + col];
        }
        __syncthreads();

        float s[4][4];
        #pragma unroll
        for (int i = 0; i < 4; i++)
            #pragma unroll
            for (int j = 0; j < 4; j++) s[i][j] = 0.f;
        #pragma unroll 4
        for (int k = 0; k < NHS; k++) {
            float4 a4 = *reinterpret_cast<const float4*>(&sQT[k * 68 + ty * 4]);
            float a[4] = {a4.x, a4.y, a4.z, a4.w};
            float b[4];
            #pragma unroll
            for (int j = 0; j < 4; j++) b[j] = sKV[(4 * tx + j) * 129 + k];
            #pragma unroll
            for (int i = 0; i < 4; i++)
                #pragma unroll
                for (int j = 0; j < 4; j++)
                    s[i][j] = fmaf(a[i], b[j], s[i][j]);
        }
        if (c == qblock) {
            #pragma unroll
            for (int i = 0; i < 4; i++)
                #pragma unroll
                for (int j = 0; j < 4; j++)
                    if (4 * tx + j > 4 * ty + i) s[i][j] = -1e30f;
        }
        #pragma unroll
        for (int i = 0; i < 4; i++) {
            float rm = fmaxf(fmaxf(s[i][0], s[i][1]), fmaxf(s[i][2], s[i][3]));
            red[(4 * ty + i) * 16 + tx] = rm;
        }
        __syncthreads();
        if (tid < 64) {
            float m = red[tid * 16];
            #pragma unroll
            for (int r = 1; r < 16; r++) m = fmaxf(m, red[tid * 16 + r]);
            float m_old = srm[tid];
            float m_new = fmaxf(m_old, m);
            sfac[tid] = __expf(m_old - m_new);
            srm[tid]  = m_new;
        }
        __syncthreads();

        #pragma unroll
        for (int i = 0; i < 4; i++) {
            int r = 4 * ty + i;
            float mr = srm[r];
            float sum = 0.f;
            #pragma unroll
            for (int j = 0; j < 4; j++) {
                float p = __expf(s[i][j] - mr);
                sP[r * 65 + 4 * tx + j] = p;
                sum += p;
            }
            red[r * 16 + tx] = sum;
        }
        const float4* vg = reinterpret_cast<const float4*>(
            &g_v[(rowbase + (size_t)c * 64) * NHS]);
        #pragma unroll
        for (int u = 0; u < 8; u++) {
            int f4 = u * 256 + tid;
            reinterpret_cast<float4*>(sKV)[f4] = vg[f4];
        }
        __syncthreads();
        if (tid < 64) {
            float sum = red[tid * 16];
            #pragma unroll
            for (int r = 1; r < 16; r++) sum += red[tid * 16 + r];
            srl[tid] = srl[tid] * sfac[tid] + sum;
        }
        #pragma unroll
        for (int i = 0; i < 4; i++) {
            float f = sfac[4 * ty + i];
            #pragma unroll
            for (int j = 0; j < 8; j++) O[i][j] *= f;
        }
        #pragma unroll 4
        for (int key = 0; key < 64; key++) {
            float a[4];
            #pragma unroll
            for (int i = 0; i < 4; i++) a[i] = sP[(4 * ty + i) * 65 + key];
            float4 b0 = *reinterpret_cast<const float4*>(&sKV[key * 128 + tx * 8]);
            float4 b1 = *reinterpret_cast<const float4*>(&sKV[key * 128 + tx * 8 + 4]);
            float b[8] = {b0.x, b0.y, b0.z, b0.w, b1.x, b1.y, b1.z, b1.w};
            #pragma unroll
            for (int i = 0; i < 4; i++)
                #pragma unroll
                for (int j = 0; j < 8; j++)
                    O[i][j] = fmaf(a[i], b[j], O[i][j]);
        }
    }
    __syncthreads();
    #pragma unroll
    for (int i = 0; i < 4; i++) {
        int r = 4 * ty + i;
        float inv = 1.f / srl[r];
        float* orow = &out[(rowbase + q0 + r) * NHS + tx * 8];
        #pragma unroll
        for (int j = 0; j < 8; j++) orow[j] = O[i][j] * inv;
    }
}

// ---------------------------------------------------------------------------
extern "C" void kernel_launch(void* const* d_in, const int* in_sizes, int n_in,
                              void* d_out, int out_size)
{
    const float* x  = (const float*)d_in[0];
    const float* Wk = (const float*)d_in[1];
    const float* Wq = (const float*)d_in[2];
    const float* Wv = (const float*)d_in[3];
    float* out = (float*)d_out;

    (void)in_sizes; (void)n_in; (void)out_size;

    const size_t attn_smem = SMEM_ATTN_FLOATS * sizeof(float);
    cudaFuncSetAttribute(attn_kernel,
                         cudaFuncAttributeMaxDynamicSharedMemorySize,
                         (int)attn_smem);

    proj_rope_mma<<<dim3(NM / 128, 3), 256>>>(x, Wk, Wq, Wv);
    attn_kernel<<<dim3(NT / 64, NB), 256, attn_smem>>>(out);
}

// round 4
// speedup vs baseline: 3.3557x; 1.7978x over previous
#include <cuda_runtime.h>
#include <math.h>
#include <stdint.h>

#define NB 8
#define NT 2048
#define NC 2048
#define NHS 128
#define NM (NB*NT)

// scratch
__device__ float g_q[(size_t)NM*NHS];                 // roped q  [b*t][hs]
__device__ float g_k[(size_t)NM*NHS];                 // roped k  [b*t][hs]
__device__ float g_vT[(size_t)NB*NHS*NT];             // v transposed [b][hs][t]
__device__ float g_cos[NT*64];
__device__ float g_sin[NT*64];

__device__ __forceinline__ uint32_t f2tf(float f) {
    uint32_t r;
    asm("cvt.rna.tf32.f32 %0, %1;" : "=r"(r) : "f"(f));
    return r;
}

__device__ __forceinline__ void mma_tf32(float c[4], const uint32_t a[4],
                                         const uint32_t b[2]) {
    asm volatile(
        "mma.sync.aligned.m16n8k8.row.col.f32.tf32.tf32.f32 "
        "{%0,%1,%2,%3}, {%4,%5,%6,%7}, {%8,%9}, {%0,%1,%2,%3};"
        : "+f"(c[0]), "+f"(c[1]), "+f"(c[2]), "+f"(c[3])
        : "r"(a[0]), "r"(a[1]), "r"(a[2]), "r"(a[3]),
          "r"(b[0]), "r"(b[1]));
}

// ---------------------------------------------------------------------------
// RoPE tables
// ---------------------------------------------------------------------------
__global__ void rope_table_kernel()
{
    int idx = blockIdx.x * 256 + threadIdx.x;
    if (idx >= NT * 64) return;
    int tt = idx >> 6, p = idx & 63;
    const float L2T = 13.287712379549449f / 64.f;   // log2(10000)/64
    float freq = exp2f(-(float)p * L2T);
    float sn, cs;
    sincosf((float)tt * freq, &sn, &cs);
    g_cos[idx] = cs;
    g_sin[idx] = sn;
}

// ---------------------------------------------------------------------------
// Kernel A: fused projection + RoPE with tf32 mma.sync.
// grid (NM/128, 3): y=0 -> k (rope), y=1 -> q (rope), y=2 -> v (transposed).
// ---------------------------------------------------------------------------
__global__ __launch_bounds__(256) void proj_rope_mma(
    const float* __restrict__ x, const float* __restrict__ Wk,
    const float* __restrict__ Wq, const float* __restrict__ Wv)
{
    constexpr int BK = 16;
    __shared__ uint32_t sA[128][20];
    __shared__ uint32_t sB[16][136];

    const int tid  = threadIdx.x;
    const int warp = tid >> 5, lane = tid & 31;
    const int wm = warp >> 2, wn = warp & 3;
    const int g = lane >> 2, t = lane & 3;
    const int mbase = blockIdx.x * 128;
    const int which = blockIdx.y;
    const float* W = (which == 0) ? Wk : (which == 1) ? Wq : Wv;

    float c[4][4][4];
    #pragma unroll
    for (int im = 0; im < 4; im++)
        #pragma unroll
        for (int in = 0; in < 4; in++)
            #pragma unroll
            for (int f = 0; f < 4; f++) c[im][in][f] = 0.f;

    float4 pa[2], pb[2];
    #pragma unroll
    for (int u = 0; u < 2; u++) {
        int idx = u * 256 + tid;
        int row = idx >> 2, cf = idx & 3;
        pa[u] = *reinterpret_cast<const float4*>(&x[(size_t)(mbase + row) * NC + cf * 4]);
    }
    #pragma unroll
    for (int u = 0; u < 2; u++) {
        int idx = u * 256 + tid;
        int krow = idx >> 5, cf = idx & 31;
        pb[u] = *reinterpret_cast<const float4*>(&W[(size_t)krow * NHS + cf * 4]);
    }

    for (int it = 0; it < NC / BK; it++) {
        #pragma unroll
        for (int u = 0; u < 2; u++) {
            int idx = u * 256 + tid;
            int row = idx >> 2, cf = idx & 3;
            sA[row][cf*4+0] = f2tf(pa[u].x); sA[row][cf*4+1] = f2tf(pa[u].y);
            sA[row][cf*4+2] = f2tf(pa[u].z); sA[row][cf*4+3] = f2tf(pa[u].w);
        }
        #pragma unroll
        for (int u = 0; u < 2; u++) {
            int idx = u * 256 + tid;
            int krow = idx >> 5, cf = idx & 31;
            sB[krow][cf*4+0] = f2tf(pb[u].x); sB[krow][cf*4+1] = f2tf(pb[u].y);
            sB[krow][cf*4+2] = f2tf(pb[u].z); sB[krow][cf*4+3] = f2tf(pb[u].w);
        }
        __syncthreads();

        if (it + 1 < NC / BK) {
            int kt = (it + 1) * BK;
            #pragma unroll
            for (int u = 0; u < 2; u++) {
                int idx = u * 256 + tid;
                int row = idx >> 2, cf = idx & 3;
                pa[u] = *reinterpret_cast<const float4*>(
                    &x[(size_t)(mbase + row) * NC + kt + cf * 4]);
            }
            #pragma unroll
            for (int u = 0; u < 2; u++) {
                int idx = u * 256 + tid;
                int krow = idx >> 5, cf = idx & 31;
                pb[u] = *reinterpret_cast<const float4*>(
                    &W[(size_t)(kt + krow) * NHS + cf * 4]);
            }
        }

        #pragma unroll
        for (int ks = 0; ks < 2; ks++) {
            int kb = ks * 8;
            uint32_t afr[4][4];
            #pragma unroll
            for (int im = 0; im < 4; im++) {
                int r0 = wm * 64 + im * 16 + g;
                afr[im][0] = sA[r0    ][kb + t    ];
                afr[im][1] = sA[r0 + 8][kb + t    ];
                afr[im][2] = sA[r0    ][kb + t + 4];
                afr[im][3] = sA[r0 + 8][kb + t + 4];
            }
            uint32_t bfr[4][2];
            #pragma unroll
            for (int in = 0; in < 4; in++) {
                int n0 = wn * 32 + in * 8 + g;
                bfr[in][0] = sB[kb + t    ][n0];
                bfr[in][1] = sB[kb + t + 4][n0];
            }
            #pragma unroll
            for (int im = 0; im < 4; im++)
                #pragma unroll
                for (int in = 0; in < 4; in++)
                    mma_tf32(c[im][in], afr[im], bfr[in]);
        }
        __syncthreads();
    }

    // epilogue
    #pragma unroll
    for (int im = 0; im < 4; im++) {
        int r1 = mbase + wm * 64 + im * 16 + g;
        int r2 = r1 + 8;
        int bb = r1 >> 11;
        int t1 = r1 & (NT - 1), t2 = r2 & (NT - 1);
        #pragma unroll
        for (int in = 0; in < 4; in++) {
            int n = wn * 32 + in * 8 + 2 * t;
            float2 lo = make_float2(c[im][in][0], c[im][in][1]);
            float2 hi = make_float2(c[im][in][2], c[im][in][3]);
            if (which == 2) {
                g_vT[((size_t)bb * NHS + n    ) * NT + t1] = lo.x;
                g_vT[((size_t)bb * NHS + n + 1) * NT + t1] = lo.y;
                g_vT[((size_t)bb * NHS + n    ) * NT + t2] = hi.x;
                g_vT[((size_t)bb * NHS + n + 1) * NT + t2] = hi.y;
            } else {
                int p = n >> 1;
                float* outp = (which == 0) ? g_k : g_q;
                float cs1 = g_cos[t1 * 64 + p], sn1 = g_sin[t1 * 64 + p];
                float cs2 = g_cos[t2 * 64 + p], sn2 = g_sin[t2 * 64 + p];
                float2 o1 = make_float2(lo.x * cs1 - lo.y * sn1,
                                        lo.x * sn1 + lo.y * cs1);
                float2 o2 = make_float2(hi.x * cs2 - hi.y * sn2,
                                        hi.x * sn2 + hi.y * cs2);
                *reinterpret_cast<float2*>(&outp[(size_t)r1 * NHS + n]) = o1;
                *reinterpret_cast<float2*>(&outp[(size_t)r2 * NHS + n]) = o2;
            }
        }
    }
}

// ---------------------------------------------------------------------------
// Kernel B: causal flash attention, tf32 mma.sync.
// grid (NT/128, NB), block 256 (8 warps). Warp w owns q rows 16w..16w+15.
// S = QK^T via 2-term tf32 split (hi*hi + hi*lo + lo*hi); PV single tf32.
// ---------------------------------------------------------------------------
#define ATTN_SMEM_BYTES ((128*132 + 2*64*132 + 128*68 + 128*68) * 4)

__global__ __launch_bounds__(256) void attn_mma(float* __restrict__ out)
{
    extern __shared__ char smem_raw[];
    float*    sQ   = (float*)smem_raw;               // [128][132] fp32, pre-scaled
    uint32_t* sKhi = (uint32_t*)(sQ + 128 * 132);    // [64][132] tf32 hi
    uint32_t* sKlo = sKhi + 64 * 132;                // [64][132] tf32 lo
    uint32_t* sVT  = sKlo + 64 * 132;                // [128][68] V^T tf32
    uint32_t* sP   = sVT + 128 * 68;                 // [128][68] P tf32

    const int tid  = threadIdx.x;
    const int warp = tid >> 5, lane = tid & 31;
    const int g = lane >> 2, t = lane & 3;
    const int r0 = warp * 16;
    const int qi = blockIdx.x, bb = blockIdx.y;
    const int q0 = qi * 128;
    const size_t rowbase = (size_t)bb * NT;
    // fold softmax scale and log2(e) into Q so we can use exp2
    const float qscale = 0.08838834764831845f * 1.4426950408889634f;

    // stage Q (coalesced gmem; smem bank conflicts here are one-time)
    #pragma unroll
    for (int u = 0; u < 16; u++) {
        int flat = u * 256 + tid;
        int row = flat >> 5, cf = flat & 31;
        float4 v = *reinterpret_cast<const float4*>(
            &g_q[(rowbase + q0 + row) * NHS + cf * 4]);
        sQ[row * 132 + cf * 4 + 0] = v.x * qscale;
        sQ[row * 132 + cf * 4 + 1] = v.y * qscale;
        sQ[row * 132 + cf * 4 + 2] = v.z * qscale;
        sQ[row * 132 + cf * 4 + 3] = v.w * qscale;
    }

    float m_lo = -1e30f, m_hi = -1e30f, l_lo = 0.f, l_hi = 0.f;
    float o[16][4];
    #pragma unroll
    for (int nt = 0; nt < 16; nt++)
        #pragma unroll
        for (int f = 0; f < 4; f++) o[nt][f] = 0.f;

    const int nchunks = 2 * qi + 2;
    for (int c = 0; c < nchunks; c++) {
        __syncthreads();
        // stage K chunk with hi/lo tf32 split
        const float* kg = &g_k[(rowbase + (size_t)c * 64) * NHS];
        #pragma unroll
        for (int u = 0; u < 8; u++) {
            int flat = u * 256 + tid;
            int row = flat >> 5, cf = flat & 31;
            float4 v = *reinterpret_cast<const float4*>(&kg[(size_t)row * NHS + cf * 4]);
            float e[4] = {v.x, v.y, v.z, v.w};
            #pragma unroll
            for (int j = 0; j < 4; j++) {
                uint32_t hi = f2tf(e[j]);
                uint32_t lo = f2tf(e[j] - __uint_as_float(hi));
                sKhi[row * 132 + cf * 4 + j] = hi;
                sKlo[row * 132 + cf * 4 + j] = lo;
            }
        }
        // stage V^T chunk (coalesced from g_vT)
        const float* vg = &g_vT[(size_t)bb * NHS * NT + (size_t)c * 64];
        #pragma unroll
        for (int u = 0; u < 8; u++) {
            int flat = u * 256 + tid;
            int hr = flat >> 4, kf = flat & 15;
            float4 v = *reinterpret_cast<const float4*>(&vg[(size_t)hr * NT + kf * 4]);
            sVT[hr * 68 + kf * 4 + 0] = f2tf(v.x);
            sVT[hr * 68 + kf * 4 + 1] = f2tf(v.y);
            sVT[hr * 68 + kf * 4 + 2] = f2tf(v.z);
            sVT[hr * 68 + kf * 4 + 3] = f2tf(v.w);
        }
        __syncthreads();

        // ---- S = QK^T (split tf32) ----
        float s[8][4];
        #pragma unroll
        for (int in = 0; in < 8; in++)
            #pragma unroll
            for (int f = 0; f < 4; f++) s[in][f] = 0.f;

        #pragma unroll
        for (int ks = 0; ks < 16; ks++) {
            int kb = ks * 8;
            float a0 = sQ[(r0 + g    ) * 132 + kb + t    ];
            float a1 = sQ[(r0 + g + 8) * 132 + kb + t    ];
            float a2 = sQ[(r0 + g    ) * 132 + kb + t + 4];
            float a3 = sQ[(r0 + g + 8) * 132 + kb + t + 4];
            uint32_t ahi[4], alo[4];
            float av[4] = {a0, a1, a2, a3};
            #pragma unroll
            for (int j = 0; j < 4; j++) {
                ahi[j] = f2tf(av[j]);
                alo[j] = f2tf(av[j] - __uint_as_float(ahi[j]));
            }
            #pragma unroll
            for (int in = 0; in < 8; in++) {
                uint32_t bh[2], bl[2];
                bh[0] = sKhi[(in * 8 + g) * 132 + kb + t    ];
                bh[1] = sKhi[(in * 8 + g) * 132 + kb + t + 4];
                bl[0] = sKlo[(in * 8 + g) * 132 + kb + t    ];
                bl[1] = sKlo[(in * 8 + g) * 132 + kb + t + 4];
                mma_tf32(s[in], ahi, bh);
                mma_tf32(s[in], ahi, bl);
                mma_tf32(s[in], alo, bh);
            }
        }

        // causal mask (only the last two chunks can cross the diagonal)
        if (c >= 2 * qi) {
            int qlo = q0 + r0 + g, qhi = qlo + 8;
            int k0c = c * 64;
            #pragma unroll
            for (int in = 0; in < 8; in++) {
                int key0 = k0c + in * 8 + 2 * t;
                if (key0     > qlo) s[in][0] = -1e30f;
                if (key0 + 1 > qlo) s[in][1] = -1e30f;
                if (key0     > qhi) s[in][2] = -1e30f;
                if (key0 + 1 > qhi) s[in][3] = -1e30f;
            }
        }

        // ---- online softmax (in-warp) ----
        float mxl = -1e30f, mxh = -1e30f;
        #pragma unroll
        for (int in = 0; in < 8; in++) {
            mxl = fmaxf(mxl, fmaxf(s[in][0], s[in][1]));
            mxh = fmaxf(mxh, fmaxf(s[in][2], s[in][3]));
        }
        mxl = fmaxf(mxl, __shfl_xor_sync(0xffffffffu, mxl, 1));
        mxl = fmaxf(mxl, __shfl_xor_sync(0xffffffffu, mxl, 2));
        mxh = fmaxf(mxh, __shfl_xor_sync(0xffffffffu, mxh, 1));
        mxh = fmaxf(mxh, __shfl_xor_sync(0xffffffffu, mxh, 2));

        float mnl = fmaxf(m_lo, mxl), mnh = fmaxf(m_hi, mxh);
        float facl = exp2f(m_lo - mnl), fach = exp2f(m_hi - mnh);
        m_lo = mnl; m_hi = mnh;

        float suml = 0.f, sumh = 0.f;
        #pragma unroll
        for (int in = 0; in < 8; in++) {
            float p0 = exp2f(s[in][0] - mnl);
            float p1 = exp2f(s[in][1] - mnl);
            float p2 = exp2f(s[in][2] - mnh);
            float p3 = exp2f(s[in][3] - mnh);
            suml += p0 + p1; sumh += p2 + p3;
            uint2 w0; w0.x = f2tf(p0); w0.y = f2tf(p1);
            uint2 w1; w1.x = f2tf(p2); w1.y = f2tf(p3);
            *reinterpret_cast<uint2*>(&sP[(r0 + g    ) * 68 + in * 8 + 2 * t]) = w0;
            *reinterpret_cast<uint2*>(&sP[(r0 + g + 8) * 68 + in * 8 + 2 * t]) = w1;
        }
        suml += __shfl_xor_sync(0xffffffffu, suml, 1);
        suml += __shfl_xor_sync(0xffffffffu, suml, 2);
        sumh += __shfl_xor_sync(0xffffffffu, sumh, 1);
        sumh += __shfl_xor_sync(0xffffffffu, sumh, 2);
        l_lo = l_lo * facl + suml;
        l_hi = l_hi * fach + sumh;

        #pragma unroll
        for (int nt = 0; nt < 16; nt++) {
            o[nt][0] *= facl; o[nt][1] *= facl;
            o[nt][2] *= fach; o[nt][3] *= fach;
        }
        __syncwarp();

        // ---- O += P V ----
        #pragma unroll
        for (int kk = 0; kk < 8; kk++) {
            int kb = kk * 8;
            uint32_t a[4];
            a[0] = sP[(r0 + g    ) * 68 + kb + t    ];
            a[1] = sP[(r0 + g + 8) * 68 + kb + t    ];
            a[2] = sP[(r0 + g    ) * 68 + kb + t + 4];
            a[3] = sP[(r0 + g + 8) * 68 + kb + t + 4];
            #pragma unroll
            for (int nt = 0; nt < 16; nt++) {
                uint32_t b[2];
                b[0] = sVT[(nt * 8 + g) * 68 + kb + t    ];
                b[1] = sVT[(nt * 8 + g) * 68 + kb + t + 4];
                mma_tf32(o[nt], a, b);
            }
        }
    }

    // epilogue
    float invl = 1.f / l_lo, invh = 1.f / l_hi;
    int qlo = q0 + r0 + g;
    #pragma unroll
    for (int nt = 0; nt < 16; nt++) {
        float2 v0 = make_float2(o[nt][0] * invl, o[nt][1] * invl);
        float2 v1 = make_float2(o[nt][2] * invh, o[nt][3] * invh);
        *reinterpret_cast<float2*>(&out[(rowbase + qlo    ) * NHS + nt * 8 + 2 * t]) = v0;
        *reinterpret_cast<float2*>(&out[(rowbase + qlo + 8) * NHS + nt * 8 + 2 * t]) = v1;
    }
}

// ---------------------------------------------------------------------------
extern "C" void kernel_launch(void* const* d_in, const int* in_sizes, int n_in,
                              void* d_out, int out_size)
{
    const float* x  = (const float*)d_in[0];
    const float* Wk = (const float*)d_in[1];
    const float* Wq = (const float*)d_in[2];
    const float* Wv = (const float*)d_in[3];
    float* out = (float*)d_out;

    (void)in_sizes; (void)n_in; (void)out_size;

    cudaFuncSetAttribute(attn_mma,
                         cudaFuncAttributeMaxDynamicSharedMemorySize,
                         ATTN_SMEM_BYTES);

    rope_table_kernel<<<(NT * 64 + 255) / 256, 256>>>();
    proj_rope_mma<<<dim3(NM / 128, 3), 256>>>(x, Wk, Wq, Wv);
    attn_mma<<<dim3(NT / 128, NB), 256, ATTN_SMEM_BYTES>>>(out);
}

// round 8
// speedup vs baseline: 3.6637x; 1.0918x over previous
#include <cuda_runtime.h>
#include <math.h>
#include <stdint.h>

#define NB 8
#define NT 2048
#define NC 2048
#define NHS 128
#define NM (NB*NT)

// scratch
__device__ float g_q[(size_t)NM*NHS];                 // roped q  [b*t][hs]
__device__ float g_k[(size_t)NM*NHS];                 // roped k  [b*t][hs]
__device__ float g_vT[(size_t)NB*NHS*NT];             // v transposed [b][hs][t]
__device__ float g_cos[NT*64];
__device__ float g_sin[NT*64];

__device__ __forceinline__ uint32_t f2tf(float f) {
    uint32_t r;
    asm("cvt.rna.tf32.f32 %0, %1;" : "=r"(r) : "f"(f));
    return r;
}

__device__ __forceinline__ void mma_tf32(float c[4], const uint32_t a[4],
                                         const uint32_t b[2]) {
    asm volatile(
        "mma.sync.aligned.m16n8k8.row.col.f32.tf32.tf32.f32 "
        "{%0,%1,%2,%3}, {%4,%5,%6,%7}, {%8,%9}, {%0,%1,%2,%3};"
        : "+f"(c[0]), "+f"(c[1]), "+f"(c[2]), "+f"(c[3])
        : "r"(a[0]), "r"(a[1]), "r"(a[2]), "r"(a[3]),
          "r"(b[0]), "r"(b[1]));
}

__device__ __forceinline__ uint32_t smem_u32(const void* p) {
    uint32_t a;
    asm("{ .reg .u64 t; cvta.to.shared.u64 t, %1; cvt.u32.u64 %0, t; }"
        : "=r"(a) : "l"(p));
    return a;
}

__device__ __forceinline__ void cp16(uint32_t dst, const void* src) {
    asm volatile("cp.async.cg.shared.global [%0], [%1], 16;"
                 :: "r"(dst), "l"(src) : "memory");
}
#define CP_COMMIT() asm volatile("cp.async.commit_group;" ::: "memory")
#define CP_WAIT(n)  asm volatile("cp.async.wait_group %0;" :: "n"(n) : "memory")

// ---------------------------------------------------------------------------
// RoPE tables
// ---------------------------------------------------------------------------
__global__ void rope_table_kernel()
{
    int idx = blockIdx.x * 256 + threadIdx.x;
    if (idx >= NT * 64) return;
    int tt = idx >> 6, p = idx & 63;
    const float L2T = 13.287712379549449f / 64.f;   // log2(10000)/64
    float freq = exp2f(-(float)p * L2T);
    float sn, cs;
    sincosf((float)tt * freq, &sn, &cs);
    g_cos[idx] = cs;
    g_sin[idx] = sn;
}

__global__ void nop_kernel() {}

// ---------------------------------------------------------------------------
// Kernel A: fused projection + RoPE. tf32 mma.sync, cp.async 3-stage pipeline.
// grid (NM/128, 3): y=0 -> k (rope), y=1 -> q (rope), y=2 -> v (transposed).
// block 256 = 8 warps (2m x 4n), warp tile 64x32, BK=32, 2 CTAs/SM.
// ---------------------------------------------------------------------------
#define PBK 32
#define ASTR 36                     // A row stride (words): (4g+t) distinct mod 32
#define BSTR 136                    // B row stride (words): (8t+g) distinct mod 32
#define AWORDS (128*ASTR)           // 4608
#define BWORDS (PBK*BSTR)           // 4352
#define STGW (AWORDS + BWORDS)      // 8960 words = 35840 B
#define PROJ_SMEM (3*STGW*4)        // 107520 B
#define NITER (NC/PBK)              // 64

__global__ __launch_bounds__(256, 2) void proj_cp(
    const float* __restrict__ x, const float* __restrict__ Wk,
    const float* __restrict__ Wq, const float* __restrict__ Wv)
{
    extern __shared__ float sm[];
    const uint32_t sbase = smem_u32(sm);

    const int tid  = threadIdx.x;
    const int warp = tid >> 5, lane = tid & 31;
    const int wm = warp >> 2, wn = warp & 3;      // 2 x 4 warp grid
    const int g = lane >> 2, t = lane & 3;
    const int mbase = blockIdx.x * 128;
    const int which = blockIdx.y;
    const float* W = (which == 0) ? Wk : (which == 1) ? Wq : Wv;

    float c[4][4][4];
    #pragma unroll
    for (int im = 0; im < 4; im++)
        #pragma unroll
        for (int in = 0; in < 4; in++)
            #pragma unroll
            for (int f = 0; f < 4; f++) c[im][in][f] = 0.f;

    // per-thread staging coords (A: 4 rows x 16B; B: 4 full-row segments)
    const int arow = tid >> 3, aq = tid & 7;

    auto stage = [&](int it, int s) {
        const int k0 = it * PBK;
        uint32_t ab = sbase + (uint32_t)(s * STGW) * 4;
        uint32_t bb = ab + (uint32_t)AWORDS * 4;
        // A: 128 rows x 32 k = 1024 float4
        #pragma unroll
        for (int u = 0; u < 4; u++) {
            int row = arow + u * 32;
            cp16(ab + (uint32_t)(row * ASTR + aq * 4) * 4,
                 &x[(size_t)(mbase + row) * NC + k0 + aq * 4]);
        }
        // B: 32 k-rows x 128 n = 1024 float4 (each warp: one full row per u)
        #pragma unroll
        for (int u = 0; u < 4; u++) {
            int flat = u * 256 + tid;
            int row = flat >> 5, cf = flat & 31;
            cp16(bb + (uint32_t)(row * BSTR + cf * 4) * 4,
                 &W[(size_t)(k0 + row) * NHS + cf * 4]);
        }
        CP_COMMIT();
    };

    stage(0, 0);
    stage(1, 1);

    for (int it = 0; it < NITER; it++) {
        if (it == NITER - 1) { CP_WAIT(0); } else { CP_WAIT(1); }
        __syncthreads();
        if (it + 2 < NITER) stage(it + 2, (it + 2) % 3);

        const float* As = sm + (size_t)((it % 3) * STGW);
        const float* Bs = As + AWORDS;

        #pragma unroll
        for (int ks = 0; ks < 4; ks++) {
            int kb = ks * 8;
            uint32_t afr[4][4];
            #pragma unroll
            for (int im = 0; im < 4; im++) {
                int r = wm * 64 + im * 16 + g;
                afr[im][0] = f2tf(As[(r    ) * ASTR + kb + t    ]);
                afr[im][1] = f2tf(As[(r + 8) * ASTR + kb + t    ]);
                afr[im][2] = f2tf(As[(r    ) * ASTR + kb + t + 4]);
                afr[im][3] = f2tf(As[(r + 8) * ASTR + kb + t + 4]);
            }
            uint32_t bfr[4][2];
            #pragma unroll
            for (int in = 0; in < 4; in++) {
                int n0 = wn * 32 + in * 8 + g;
                bfr[in][0] = f2tf(Bs[(kb + t    ) * BSTR + n0]);
                bfr[in][1] = f2tf(Bs[(kb + t + 4) * BSTR + n0]);
            }
            #pragma unroll
            for (int im = 0; im < 4; im++)
                #pragma unroll
                for (int in = 0; in < 4; in++)
                    mma_tf32(c[im][in], afr[im], bfr[in]);
        }
        __syncthreads();
    }

    // epilogue: RoPE for q/k, transposed store for v.
    #pragma unroll
    for (int im = 0; im < 4; im++) {
        int r1 = mbase + wm * 64 + im * 16 + g;
        int r2 = r1 + 8;
        int bb = r1 >> 11;
        int t1 = r1 & (NT - 1), t2 = r2 & (NT - 1);
        #pragma unroll
        for (int in = 0; in < 4; in++) {
            int n = wn * 32 + in * 8 + 2 * t;
            float2 lo = make_float2(c[im][in][0], c[im][in][1]);
            float2 hi = make_float2(c[im][in][2], c[im][in][3]);
            if (which == 2) {
                g_vT[((size_t)bb * NHS + n    ) * NT + t1] = lo.x;
                g_vT[((size_t)bb * NHS + n + 1) * NT + t1] = lo.y;
                g_vT[((size_t)bb * NHS + n    ) * NT + t2] = hi.x;
                g_vT[((size_t)bb * NHS + n + 1) * NT + t2] = hi.y;
            } else {
                int p = n >> 1;
                float* outp = (which == 0) ? g_k : g_q;
                float cs1 = g_cos[t1 * 64 + p], sn1 = g_sin[t1 * 64 + p];
                float cs2 = g_cos[t2 * 64 + p], sn2 = g_sin[t2 * 64 + p];
                float2 o1 = make_float2(lo.x * cs1 - lo.y * sn1,
                                        lo.x * sn1 + lo.y * cs1);
                float2 o2 = make_float2(hi.x * cs2 - hi.y * sn2,
                                        hi.x * sn2 + hi.y * cs2);
                *reinterpret_cast<float2*>(&outp[(size_t)r1 * NHS + n]) = o1;
                *reinterpret_cast<float2*>(&outp[(size_t)r2 * NHS + n]) = o2;
            }
        }
    }
}

// ---------------------------------------------------------------------------
// Kernel B: causal flash attention, tf32 mma.sync.  (unchanged)
// ---------------------------------------------------------------------------
#define ATTN_SMEM_BYTES ((128*132 + 2*64*132 + 128*68 + 128*68) * 4)

__global__ __launch_bounds__(256) void attn_mma(float* __restrict__ out)
{
    extern __shared__ char smem_raw[];
    float*    sQ   = (float*)smem_raw;               // [128][132] fp32, pre-scaled
    uint32_t* sKhi = (uint32_t*)(sQ + 128 * 132);    // [64][132] tf32 hi
    uint32_t* sKlo = sKhi + 64 * 132;                // [64][132] tf32 lo
    uint32_t* sVT  = sKlo + 64 * 132;                // [128][68] V^T tf32
    uint32_t* sP   = sVT + 128 * 68;                 // [128][68] P tf32

    const int tid  = threadIdx.x;
    const int warp = tid >> 5, lane = tid & 31;
    const int g = lane >> 2, t = lane & 3;
    const int r0 = warp * 16;
    const int qi = blockIdx.x, bb = blockIdx.y;
    const int q0 = qi * 128;
    const size_t rowbase = (size_t)bb * NT;
    const float qscale = 0.08838834764831845f * 1.4426950408889634f;

    #pragma unroll
    for (int u = 0; u < 16; u++) {
        int flat = u * 256 + tid;
        int row = flat >> 5, cf = flat & 31;
        float4 v = *reinterpret_cast<const float4*>(
            &g_q[(rowbase + q0 + row) * NHS + cf * 4]);
        sQ[row * 132 + cf * 4 + 0] = v.x * qscale;
        sQ[row * 132 + cf * 4 + 1] = v.y * qscale;
        sQ[row * 132 + cf * 4 + 2] = v.z * qscale;
        sQ[row * 132 + cf * 4 + 3] = v.w * qscale;
    }

    float m_lo = -1e30f, m_hi = -1e30f, l_lo = 0.f, l_hi = 0.f;
    float o[16][4];
    #pragma unroll
    for (int nt = 0; nt < 16; nt++)
        #pragma unroll
        for (int f = 0; f < 4; f++) o[nt][f] = 0.f;

    const int nchunks = 2 * qi + 2;
    for (int c = 0; c < nchunks; c++) {
        __syncthreads();
        const float* kg = &g_k[(rowbase + (size_t)c * 64) * NHS];
        #pragma unroll
        for (int u = 0; u < 8; u++) {
            int flat = u * 256 + tid;
            int row = flat >> 5, cf = flat & 31;
            float4 v = *reinterpret_cast<const float4*>(&kg[(size_t)row * NHS + cf * 4]);
            float e[4] = {v.x, v.y, v.z, v.w};
            #pragma unroll
            for (int j = 0; j < 4; j++) {
                uint32_t hi = f2tf(e[j]);
                uint32_t lo = f2tf(e[j] - __uint_as_float(hi));
                sKhi[row * 132 + cf * 4 + j] = hi;
                sKlo[row * 132 + cf * 4 + j] = lo;
            }
        }
        const float* vg = &g_vT[(size_t)bb * NHS * NT + (size_t)c * 64];
        #pragma unroll
        for (int u = 0; u < 8; u++) {
            int flat = u * 256 + tid;
            int hr = flat >> 4, kf = flat & 15;
            float4 v = *reinterpret_cast<const float4*>(&vg[(size_t)hr * NT + kf * 4]);
            sVT[hr * 68 + kf * 4 + 0] = f2tf(v.x);
            sVT[hr * 68 + kf * 4 + 1] = f2tf(v.y);
            sVT[hr * 68 + kf * 4 + 2] = f2tf(v.z);
            sVT[hr * 68 + kf * 4 + 3] = f2tf(v.w);
        }
        __syncthreads();

        float s[8][4];
        #pragma unroll
        for (int in = 0; in < 8; in++)
            #pragma unroll
            for (int f = 0; f < 4; f++) s[in][f] = 0.f;

        #pragma unroll
        for (int ks = 0; ks < 16; ks++) {
            int kb = ks * 8;
            float a0 = sQ[(r0 + g    ) * 132 + kb + t    ];
            float a1 = sQ[(r0 + g + 8) * 132 + kb + t    ];
            float a2 = sQ[(r0 + g    ) * 132 + kb + t + 4];
            float a3 = sQ[(r0 + g + 8) * 132 + kb + t + 4];
            uint32_t ahi[4], alo[4];
            float av[4] = {a0, a1, a2, a3};
            #pragma unroll
            for (int j = 0; j < 4; j++) {
                ahi[j] = f2tf(av[j]);
                alo[j] = f2tf(av[j] - __uint_as_float(ahi[j]));
            }
            #pragma unroll
            for (int in = 0; in < 8; in++) {
                uint32_t bh[2], bl[2];
                bh[0] = sKhi[(in * 8 + g) * 132 + kb + t    ];
                bh[1] = sKhi[(in * 8 + g) * 132 + kb + t + 4];
                bl[0] = sKlo[(in * 8 + g) * 132 + kb + t    ];
                bl[1] = sKlo[(in * 8 + g) * 132 + kb + t + 4];
                mma_tf32(s[in], ahi, bh);
                mma_tf32(s[in], ahi, bl);
                mma_tf32(s[in], alo, bh);
            }
        }

        if (c >= 2 * qi) {
            int qlo = q0 + r0 + g, qhi = qlo + 8;
            int k0c = c * 64;
            #pragma unroll
            for (int in = 0; in < 8; in++) {
                int key0 = k0c + in * 8 + 2 * t;
                if (key0     > qlo) s[in][0] = -1e30f;
                if (key0 + 1 > qlo) s[in][1] = -1e30f;
                if (key0     > qhi) s[in][2] = -1e30f;
                if (key0 + 1 > qhi) s[in][3] = -1e30f;
            }
        }

        float mxl = -1e30f, mxh = -1e30f;
        #pragma unroll
        for (int in = 0; in < 8; in++) {
            mxl = fmaxf(mxl, fmaxf(s[in][0], s[in][1]));
            mxh = fmaxf(mxh, fmaxf(s[in][2], s[in][3]));
        }
        mxl = fmaxf(mxl, __shfl_xor_sync(0xffffffffu, mxl, 1));
        mxl = fmaxf(mxl, __shfl_xor_sync(0xffffffffu, mxl, 2));
        mxh = fmaxf(mxh, __shfl_xor_sync(0xffffffffu, mxh, 1));
        mxh = fmaxf(mxh, __shfl_xor_sync(0xffffffffu, mxh, 2));

        float mnl = fmaxf(m_lo, mxl), mnh = fmaxf(m_hi, mxh);
        float facl = exp2f(m_lo - mnl), fach = exp2f(m_hi - mnh);
        m_lo = mnl; m_hi = mnh;

        float suml = 0.f, sumh = 0.f;
        #pragma unroll
        for (int in = 0; in < 8; in++) {
            float p0 = exp2f(s[in][0] - mnl);
            float p1 = exp2f(s[in][1] - mnl);
            float p2 = exp2f(s[in][2] - mnh);
            float p3 = exp2f(s[in][3] - mnh);
            suml += p0 + p1; sumh += p2 + p3;
            uint2 w0; w0.x = f2tf(p0); w0.y = f2tf(p1);
            uint2 w1; w1.x = f2tf(p2); w1.y = f2tf(p3);
            *reinterpret_cast<uint2*>(&sP[(r0 + g    ) * 68 + in * 8 + 2 * t]) = w0;
            *reinterpret_cast<uint2*>(&sP[(r0 + g + 8) * 68 + in * 8 + 2 * t]) = w1;
        }
        suml += __shfl_xor_sync(0xffffffffu, suml, 1);
        suml += __shfl_xor_sync(0xffffffffu, suml, 2);
        sumh += __shfl_xor_sync(0xffffffffu, sumh, 1);
        sumh += __shfl_xor_sync(0xffffffffu, sumh, 2);
        l_lo = l_lo * facl + suml;
        l_hi = l_hi * fach + sumh;

        #pragma unroll
        for (int nt = 0; nt < 16; nt++) {
            o[nt][0] *= facl; o[nt][1] *= facl;
            o[nt][2] *= fach; o[nt][3] *= fach;
        }
        __syncwarp();

        #pragma unroll
        for (int kk = 0; kk < 8; kk++) {
            int kb = kk * 8;
            uint32_t a[4];
            a[0] = sP[(r0 + g    ) * 68 + kb + t    ];
            a[1] = sP[(r0 + g + 8) * 68 + kb + t    ];
            a[2] = sP[(r0 + g    ) * 68 + kb + t + 4];
            a[3] = sP[(r0 + g + 8) * 68 + kb + t + 4];
            #pragma unroll
            for (int nt = 0; nt < 16; nt++) {
                uint32_t b[2];
                b[0] = sVT[(nt * 8 + g) * 68 + kb + t    ];
                b[1] = sVT[(nt * 8 + g) * 68 + kb + t + 4];
                mma_tf32(o[nt], a, b);
            }
        }
    }

    float invl = 1.f / l_lo, invh = 1.f / l_hi;
    int qlo = q0 + r0 + g;
    #pragma unroll
    for (int nt = 0; nt < 16; nt++) {
        float2 v0 = make_float2(o[nt][0] * invl, o[nt][1] * invl);
        float2 v1 = make_float2(o[nt][2] * invh, o[nt][3] * invh);
        *reinterpret_cast<float2*>(&out[(rowbase + qlo    ) * NHS + nt * 8 + 2 * t]) = v0;
        *reinterpret_cast<float2*>(&out[(rowbase + qlo + 8) * NHS + nt * 8 + 2 * t]) = v1;
    }
}

// ---------------------------------------------------------------------------
extern "C" void kernel_launch(void* const* d_in, const int* in_sizes, int n_in,
                              void* d_out, int out_size)
{
    const float* x  = (const float*)d_in[0];
    const float* Wk = (const float*)d_in[1];
    const float* Wq = (const float*)d_in[2];
    const float* Wv = (const float*)d_in[3];
    float* out = (float*)d_out;

    (void)in_sizes; (void)n_in; (void)out_size;

    cudaFuncSetAttribute(attn_mma,
                         cudaFuncAttributeMaxDynamicSharedMemorySize,
                         ATTN_SMEM_BYTES);
    cudaFuncSetAttribute(proj_cp,
                         cudaFuncAttributeMaxDynamicSharedMemorySize,
                         PROJ_SMEM);

    rope_table_kernel<<<(NT * 64 + 255) / 256, 256>>>();
    proj_cp<<<dim3(NM / 128, 3), 256, PROJ_SMEM>>>(x, Wk, Wq, Wv);
    attn_mma<<<dim3(NT / 128, NB), 256, ATTN_SMEM_BYTES>>>(out);
    nop_kernel<<<1, 32>>>();   // shifts ncu -s 5 onto proj_cp next capture
}